// round 1
// baseline (speedup 1.0000x reference)
#include <cuda_runtime.h>

// Problem constants (fixed shapes from reference)
#define TS    4096          // sequence length S
#define NH    16            // heads
#define HD    128           // head dim
#define NP    512           // prompt length P
#define NR    2             // regions
#define BM    64            // query tile
#define BN    64            // key chunk
#define BNP   68            // padded row for K^T in smem
#define PPAD  68            // padded row for P in smem
#define NT    256           // threads per CTA
#define KVSTRIDE (NH*HD)    // stride between consecutive keys in gmem (B=1)
#define SCALE 0.08838834764831845f  // 1/sqrt(128)

__device__ __forceinline__ float redmax16(float v) {
  v = fmaxf(v, __shfl_xor_sync(0xffffffffu, v, 1));
  v = fmaxf(v, __shfl_xor_sync(0xffffffffu, v, 2));
  v = fmaxf(v, __shfl_xor_sync(0xffffffffu, v, 4));
  v = fmaxf(v, __shfl_xor_sync(0xffffffffu, v, 8));
  return v;
}
__device__ __forceinline__ float redsum16(float v) {
  v += __shfl_xor_sync(0xffffffffu, v, 1);
  v += __shfl_xor_sync(0xffffffffu, v, 2);
  v += __shfl_xor_sync(0xffffffffu, v, 4);
  v += __shfl_xor_sync(0xffffffffu, v, 8);
  return v;
}

// Process one 64-key chunk against the 64-query tile with online softmax.
// act[qi] == 0  -> this chunk is fully masked for that query (contributes nothing).
__device__ __forceinline__ void process_chunk(
    const float* __restrict__ kc, const float* __restrict__ vc,
    const unsigned (&act)[4],
    float (&m)[4], float (&l)[4], float (&acc)[4][8],
    const float* __restrict__ sQ, float* __restrict__ sKt,
    float* __restrict__ sV, float* __restrict__ sP,
    int tid, int ty, int tx)
{
  const int q0 = ty * 4;
  const int k0 = tx * 4;
  const int dc = tx * 8;

  __syncthreads();   // previous chunk's consumers done with sKt/sV/sP

  // Load K (transposed) and V into smem. One warp covers exactly one key row
  // per iteration (32 float4 = 128 floats).
  #pragma unroll
  for (int i = 0; i < 8; i++) {
    int f  = tid + i * NT;        // float4 index over 64x128 tile
    int j  = f >> 5;              // key within chunk
    int d0 = (f & 31) << 2;       // dim
    float4 kk = *(const float4*)(kc + (size_t)j * KVSTRIDE + d0);
    sKt[(d0 + 0) * BNP + j] = kk.x;
    sKt[(d0 + 1) * BNP + j] = kk.y;
    sKt[(d0 + 2) * BNP + j] = kk.z;
    sKt[(d0 + 3) * BNP + j] = kk.w;
    *(float4*)&sV[j * HD + d0] = *(const float4*)(vc + (size_t)j * KVSTRIDE + d0);
  }
  __syncthreads();

  // Scores: 4 queries x 4 keys per thread, K=128
  float sc[4][4];
  #pragma unroll
  for (int a = 0; a < 4; a++)
    #pragma unroll
    for (int b = 0; b < 4; b++) sc[a][b] = 0.f;

  #pragma unroll 8
  for (int d0 = 0; d0 < HD; d0 += 4) {
    float4 qv[4], kv[4];
    #pragma unroll
    for (int qi = 0; qi < 4; qi++)
      qv[qi] = *(const float4*)&sQ[(q0 + qi) * HD + d0];
    #pragma unroll
    for (int dd = 0; dd < 4; dd++)
      kv[dd] = *(const float4*)&sKt[(d0 + dd) * BNP + k0];
    #pragma unroll
    for (int qi = 0; qi < 4; qi++) {
      const float* qf = (const float*)&qv[qi];
      #pragma unroll
      for (int dd = 0; dd < 4; dd++) {
        const float* kf = (const float*)&kv[dd];
        float qq = qf[dd];
        #pragma unroll
        for (int kj = 0; kj < 4; kj++)
          sc[qi][kj] = fmaf(qq, kf[kj], sc[qi][kj]);
      }
    }
  }

  // Online softmax update (per query; stats replicated across the 16 tx lanes)
  #pragma unroll
  for (int qi = 0; qi < 4; qi++) {
    bool a = (act[qi] != 0u);
    float rmax = fmaxf(fmaxf(sc[qi][0], sc[qi][1]), fmaxf(sc[qi][2], sc[qi][3]));
    rmax = redmax16(rmax);
    float mold = m[qi];
    float mnew = a ? fmaxf(mold, rmax) : mold;
    float corr = __expf(mold - mnew);   // ==1 if unchanged; ==0 on first active chunk (mold=-1e30)
    float ps = 0.f;
    #pragma unroll
    for (int kj = 0; kj < 4; kj++) {
      float p = a ? __expf(sc[qi][kj] - mnew) : 0.f;
      sc[qi][kj] = p;
      ps += p;
    }
    ps = redsum16(ps);
    l[qi] = l[qi] * corr + ps;
    m[qi] = mnew;
    #pragma unroll
    for (int dd = 0; dd < 8; dd++) acc[qi][dd] *= corr;
    *(float4*)&sP[(q0 + qi) * PPAD + k0] =
        make_float4(sc[qi][0], sc[qi][1], sc[qi][2], sc[qi][3]);
  }
  __syncthreads();

  // PV: acc[qi][0..7] += sum_j P[qi][j] * V[j][dc..dc+7]
  #pragma unroll 4
  for (int j = 0; j < BN; j++) {
    float4 v0 = *(const float4*)&sV[j * HD + dc];
    float4 v1 = *(const float4*)&sV[j * HD + dc + 4];
    #pragma unroll
    for (int qi = 0; qi < 4; qi++) {
      float p = sP[(q0 + qi) * PPAD + j];
      acc[qi][0] = fmaf(p, v0.x, acc[qi][0]);
      acc[qi][1] = fmaf(p, v0.y, acc[qi][1]);
      acc[qi][2] = fmaf(p, v0.z, acc[qi][2]);
      acc[qi][3] = fmaf(p, v0.w, acc[qi][3]);
      acc[qi][4] = fmaf(p, v1.x, acc[qi][4]);
      acc[qi][5] = fmaf(p, v1.y, acc[qi][5]);
      acc[qi][6] = fmaf(p, v1.z, acc[qi][6]);
      acc[qi][7] = fmaf(p, v1.w, acc[qi][7]);
    }
  }
}

__global__ __launch_bounds__(NT, 1)
void regional_attn_kernel(const float* __restrict__ q,
                          const float* __restrict__ k,
                          const float* __restrict__ v,
                          const float* __restrict__ rk,
                          const float* __restrict__ rv,
                          const int*  __restrict__ masks,
                          float* __restrict__ out)
{
  extern __shared__ float sm[];
  float* sQ  = sm;                     // [BM][HD]      8192 floats
  float* sKt = sQ + BM * HD;           // [HD][BNP]     8704
  float* sV  = sKt + HD * BNP;         // [BN][HD]      8192
  float* sP  = sV + BN * HD;           // [BM][PPAD]    4352

  const int tid = threadIdx.x;
  const int ty = tid >> 4;
  const int tx = tid & 15;
  const int q0 = ty * 4;
  const int dc = tx * 8;
  const int h = blockIdx.y;
  const int sBase = blockIdx.x * BM;

  // Load Q tile, pre-scaled by 1/sqrt(D)
  #pragma unroll
  for (int i = 0; i < 8; i++) {
    int f   = tid + i * NT;
    int row = f >> 5;
    int d0  = (f & 31) << 2;
    float4 qq = *(const float4*)(q + ((size_t)(sBase + row) * NH + h) * HD + d0);
    qq.x *= SCALE; qq.y *= SCALE; qq.z *= SCALE; qq.w *= SCALE;
    *(float4*)&sQ[row * HD + d0] = qq;
  }

  // Region membership bits for this thread's 4 queries
  unsigned act0[4], act1[4], actA[4];
  #pragma unroll
  for (int qi = 0; qi < 4; qi++) {
    int s = sBase + q0 + qi;
    act0[qi] = (unsigned)(masks[s] != 0);
    act1[qi] = (unsigned)(masks[TS + s] != 0);
    actA[qi] = 1u;
  }

  float mB[4], lB[4], mR[4], lR[4];
  float accB[4][8], accR[4][8];
  #pragma unroll
  for (int qi = 0; qi < 4; qi++) {
    mB[qi] = -1e30f; lB[qi] = 0.f;
    mR[qi] = -1e30f; lR[qi] = 0.f;
    #pragma unroll
    for (int dd = 0; dd < 8; dd++) { accB[qi][dd] = 0.f; accR[qi][dd] = 0.f; }
  }

  // Pass 1: base attention over k/v (always active)
  #pragma unroll 1
  for (int c = 0; c < NP / BN; c++) {
    const float* kc = k + ((size_t)(c * BN) * NH + h) * HD;
    const float* vc = v + ((size_t)(c * BN) * NH + h) * HD;
    process_chunk(kc, vc, actA, mB, lB, accB, sQ, sKt, sV, sP, tid, ty, tx);
  }

  // Pass 2: regional attention over the two regional blocks, per-query gated
  #pragma unroll 1
  for (int r = 0; r < NR; r++) {
    unsigned actR4[4];
    #pragma unroll
    for (int qi = 0; qi < 4; qi++) actR4[qi] = (r == 0) ? act0[qi] : act1[qi];
    #pragma unroll 1
    for (int c = 0; c < NP / BN; c++) {
      const float* kc = rk + ((size_t)(r * NP + c * BN) * NH + h) * HD;
      const float* vc = rv + ((size_t)(r * NP + c * BN) * NH + h) * HD;
      process_chunk(kc, vc, actR4, mR, lR, accR, sQ, sKt, sV, sP, tid, ty, tx);
    }
  }

  // Epilogue: out = 0.5*base + 0.5*(regional, falling back to base if no region)
  #pragma unroll
  for (int qi = 0; qi < 4; qi++) {
    int s = sBase + q0 + qi;
    float ib = 1.f / lB[qi];
    bool anyr = ((act0[qi] | act1[qi]) != 0u);
    float ir = anyr ? 1.f / lR[qi] : 0.f;
    float o[8];
    #pragma unroll
    for (int dd = 0; dd < 8; dd++) {
      float ob  = accB[qi][dd] * ib;
      float orr = anyr ? accR[qi][dd] * ir : ob;
      o[dd] = 0.5f * (ob + orr);
    }
    float4* dst = (float4*)(out + (size_t)s * (NH * HD) + h * HD + dc);
    dst[0] = make_float4(o[0], o[1], o[2], o[3]);
    dst[1] = make_float4(o[4], o[5], o[6], o[7]);
  }
}

extern "C" void kernel_launch(void* const* d_in, const int* in_sizes, int n_in,
                              void* d_out, int out_size)
{
  const float* q     = (const float*)d_in[0];
  const float* k     = (const float*)d_in[1];
  const float* v     = (const float*)d_in[2];
  const float* rk    = (const float*)d_in[3];
  const float* rv    = (const float*)d_in[4];
  const int*   masks = (const int*)d_in[5];
  float* out = (float*)d_out;

  const int smem = (BM * HD + HD * BNP + BN * HD + BM * PPAD) * (int)sizeof(float); // 117760
  cudaFuncSetAttribute(regional_attn_kernel,
                       cudaFuncAttributeMaxDynamicSharedMemorySize, smem);

  dim3 grid(TS / BM, NH);   // (64, 16) = 1024 CTAs
  regional_attn_kernel<<<grid, NT, smem>>>(q, k, v, rk, rv, masks, out);
}